// round 10
// baseline (speedup 1.0000x reference)
#include <cuda_runtime.h>
#include <cuda_fp16.h>
#include <cstdint>

#define HW_    3136
#define KTOT_  1152
#define NCHUNK 36          // 9 taps * 4 c-chunks of 32
#define NPIX_  112         // pixels per tile = 2 image rows
#define NITEM  896         // 28 px-tiles * 32 batches

// W in smem-image layout: [e][tap][chunk4][o 128][4 segs x 8 halves], seg pre-swizzled
__device__ __align__(16) __half g_Wq[8 * 9 * 4 * 128 * 32];
// packed x: [b][window (8 of 16ch)][58*58 px][16 halves, permuted {0,1,8,9,2,3,10,11,4,5,12,13,6,7,14,15}]
__device__ __align__(16) __half g_xq[(size_t)32 * 8 * 3364 * 16];
// work-stealing counter
__device__ int g_ctr;

__device__ __forceinline__ uint32_t smem_u32(const void* p) {
    uint32_t a;
    asm("{ .reg .u64 t; cvta.to.shared.u64 t, %1; cvt.u32.u64 %0, t; }" : "=r"(a) : "l"(p));
    return a;
}
#define MBAR_INIT(mb, c)  asm volatile("mbarrier.init.shared.b64 [%0], %1;" :: "r"(mb), "r"(c) : "memory")
#define MBAR_EXPECT(mb, tx) \
    asm volatile("mbarrier.arrive.expect_tx.shared.b64 _, [%0], %1;" :: "r"(mb), "r"(tx) : "memory")
#define BULK_G2S(dst, src, sz, mb) \
    asm volatile("cp.async.bulk.shared::cta.global.mbarrier::complete_tx::bytes [%0], [%1], %2, [%3];" \
                 :: "r"(dst), "l"(src), "r"(sz), "r"(mb) : "memory")

#define MBAR_WAIT(mb, ph) do {                                                            \
    uint32_t _m = (mb), _p = (ph), _d;                                                    \
    asm volatile("{ .reg .pred p; mbarrier.try_wait.parity.acquire.cta.shared::cta.b64 "  \
                 "p, [%1], %2; selp.b32 %0, 1, 0, p; }"                                   \
                 : "=r"(_d) : "r"(_m), "r"(_p) : "memory");                               \
    if (!_d) {                                                                            \
        asm volatile("{ .reg .pred P1;\n\t"                                               \
            "W_%=: mbarrier.try_wait.parity.acquire.cta.shared::cta.b64 P1, [%0], %1, 0x989680;\n\t" \
            "@P1 bra.uni D_%=;\n\t bra.uni W_%=;\n\t D_%=: }"                             \
            :: "r"(_m), "r"(_p) : "memory");                                              \
    } } while (0)

__device__ __forceinline__ void ldm_x4(uint32_t* r, uint32_t addr) {
    asm volatile("ldmatrix.sync.aligned.m8n8.x4.shared.b16 {%0,%1,%2,%3}, [%4];"
                 : "=r"(r[0]), "=r"(r[1]), "=r"(r[2]), "=r"(r[3]) : "r"(addr));
}
__device__ __forceinline__ void mma16816(float* d, const uint32_t* a, uint32_t b0, uint32_t b1) {
    asm volatile("mma.sync.aligned.m16n8k16.row.col.f32.f16.f16.f32 "
                 "{%0,%1,%2,%3}, {%4,%5,%6,%7}, {%8,%9}, {%0,%1,%2,%3};"
                 : "+f"(d[0]), "+f"(d[1]), "+f"(d[2]), "+f"(d[3])
                 : "r"(a[0]), "r"(a[1]), "r"(a[2]), "r"(a[3]), "r"(b0), "r"(b1));
}

__global__ void reset_ctr_kernel() { g_ctr = 0; }

// ---------------- Prep: pad + fp16 + permuted 16-channel pack ----------------
__global__ __launch_bounds__(256) void pack_kernel(const float* __restrict__ x) {
    const int wg = blockIdx.x;   // window 0..7
    const int b  = blockIdx.y;   // 0..31
    const float* xb = x + ((size_t)b * 128 + wg * 16) * HW_;
    uint32_t* dst = (uint32_t*)(g_xq + ((size_t)(b * 8 + wg)) * 3364 * 16);
    const int P[16] = {0, 1, 8, 9, 2, 3, 10, 11, 4, 5, 12, 13, 6, 7, 14, 15};
    for (int i = threadIdx.x; i < 3364; i += 256) {
        int r = i / 58;
        int c = i - r * 58;
        bool in = ((unsigned)(r - 1) < 56u) && ((unsigned)(c - 1) < 56u);
        int q = (r - 1) * 56 + (c - 1);
        uint32_t v[8];
#pragma unroll
        for (int s = 0; s < 8; s++) {
            float f0 = in ? xb[(size_t)P[2 * s] * HW_ + q] : 0.f;
            float f1 = in ? xb[(size_t)P[2 * s + 1] * HW_ + q] : 0.f;
            __half2 hp = __floats2half2_rn(f0, f1);
            v[s] = *(uint32_t*)&hp;
        }
        *(uint4*)(dst + (size_t)i * 8)     = make_uint4(v[0], v[1], v[2], v[3]);
        *(uint4*)(dst + (size_t)i * 8 + 4) = make_uint4(v[4], v[5], v[6], v[7]);
    }
}

// ---------------- Kernel A: build W_eff -> fp16, smem-image layout ----------------
__global__ __launch_bounds__(256) void build_weff_kernel(
    const float* __restrict__ wspec,   // [8][128][1152] (cdd = c*9 + tap)
    const float* __restrict__ wch)     // [8][128][256]
{
    const int e  = blockIdx.y;
    const int n0 = blockIdx.x * 128;

    __shared__ float As[8][128];
    __shared__ float Bs[8][128];

    const int t  = threadIdx.x;
    const int tm = t >> 4;
    const int tn = t & 15;

    float acc[8][8];
#pragma unroll
    for (int i = 0; i < 8; i++)
#pragma unroll
        for (int j = 0; j < 8; j++) acc[i][j] = 0.f;

    for (int kt = 0; kt < 16; ++kt) {
#pragma unroll
        for (int i = 0; i < 4; i++) {
            int idx = t + i * 256;
            int kl  = idx >> 7;
            int nl  = idx & 127;
            As[kl][nl] = wspec[(e * 128 + kt * 8 + kl) * 1152 + n0 + nl];
            Bs[kl][nl] = wch[(e * 128 + nl) * 256 + 128 + kt * 8 + kl];
        }
        __syncthreads();
#pragma unroll
        for (int kk = 0; kk < 8; kk++) {
            float a[8], bv[8];
            *(float4*)&a[0]  = *(const float4*)&As[kk][tm * 4];
            *(float4*)&a[4]  = *(const float4*)&As[kk][64 + tm * 4];
            *(float4*)&bv[0] = *(const float4*)&Bs[kk][tn * 4];
            *(float4*)&bv[4] = *(const float4*)&Bs[kk][64 + tn * 4];
#pragma unroll
            for (int i = 0; i < 8; i++)
#pragma unroll
                for (int j = 0; j < 8; j++) acc[i][j] += a[i] * bv[j];
        }
        __syncthreads();
    }

#pragma unroll
    for (int mi = 0; mi < 8; mi++) {
        int mrow = (mi < 4) ? (tm * 4 + mi) : (64 + tm * 4 + mi - 4);
        int cdd  = n0 + mrow;
        int cc   = cdd / 9;
        int tap  = cdd - cc * 9;
        bool center = (tap == 4);
        int chunk = cc >> 5;
        int pos   = cc & 31;
        int seg   = pos >> 3;
        int w8    = pos & 7;
#pragma unroll
        for (int j = 0; j < 8; j++) {
            int o = (j < 4) ? (tn * 4 + j) : (64 + tn * 4 + j - 4);
            float v = acc[mi][j];
            if (center) v += wch[(e * 128 + o) * 256 + cc];
            int segS = seg ^ ((o >> 1) & 3);
            size_t idx = ((((size_t)(e * 9 + tap) * 4 + chunk) * 128 + o) * 4 + segS) * 8 + w8;
            g_Wq[idx] = __float2half_rn(v);
        }
    }
}

// ---------------- Kernel B: persistent, work-stealing, bulk-copy fills ----------------
#define A_SZ      8192
#define B_SZ      7168
#define SLOT_SZ   (2 * A_SZ + B_SZ)               // 23552
#define NSTAGE    3
#define SMEM_TOTAL (1024 + NSTAGE * SLOT_SZ)      // 71680
#define A_OFF(buf, ex) (1024 + (buf) * SLOT_SZ + (ex) * A_SZ)
#define B_OFF(buf)     (1024 + (buf) * SLOT_SZ + 16384)

__global__ __launch_bounds__(512, 1) void conv_mma_kernel(
    const int* __restrict__ gate,     // [32][2]
    float*     __restrict__ out)      // [32][2][128][56][56]
{
    extern __shared__ char smem[];
    const uint32_t sb = smem_u32(smem);

    const int tid  = threadIdx.x;
    const int wid  = tid >> 5;
    const int lane = tid & 31;
    const int g    = lane >> 2;
    const int tq   = lane & 3;

    const int ex = wid >> 3;
    const int wg = wid & 7;
    const int mo = (wg >> 1) * 32;
    const int po = (wg & 1) * 56;
    const int orow  = lane & 15;
    const int chalf = lane >> 4;

    __shared__ int s_item;

    if (tid == 0) {
        MBAR_INIT(sb + 0, 1);
        MBAR_INIT(sb + 8, 1);
        MBAR_INIT(sb + 16, 1);
    }
    __syncthreads();

    int phase[NSTAGE] = {0, 0, 0};
    int buf = 0;

    for (;;) {
        if (tid == 0) s_item = atomicAdd(&g_ctr, 1);
        __syncthreads();
        const int item = s_item;
        if (item >= NITEM) break;

        const int b   = item & 31;
        const int pt  = item >> 5;
        const int n0  = pt * NPIX_;
        const int h0  = pt * 2;
        const int e0  = gate[2 * b];
        const int e1  = gate[2 * b + 1];
        const __half* xqb = g_xq + (size_t)b * 8 * 3364 * 16;

        float acc[2][7][4];
#pragma unroll
        for (int mt = 0; mt < 2; mt++)
#pragma unroll
            for (int j = 0; j < 7; j++)
#pragma unroll
                for (int q = 0; q < 4; q++) acc[mt][j][q] = 0.f;

        auto fillStage = [&](int slot, int ch) {
            const int tap = ch >> 2;
            const int cc  = ch & 3;
            const uint32_t mb = sb + 8 * slot;
            MBAR_EXPECT(mb, (uint32_t)SLOT_SZ);
            const __half* a0 = g_Wq + (((size_t)(e0 * 9 + tap) * 4 + cc) * 128) * 32;
            const __half* a1 = g_Wq + (((size_t)(e1 * 9 + tap) * 4 + cc) * 128) * 32;
            BULK_G2S(sb + A_OFF(slot, 0), a0, A_SZ, mb);
            BULK_G2S(sb + A_OFF(slot, 1), a1, A_SZ, mb);
            const int dy = tap / 3;
            const int dx = tap - 3 * dy;
#pragma unroll
            for (int fw = 0; fw < 2; fw++) {
                const int w16 = cc * 2 + fw;
#pragma unroll
                for (int r = 0; r < 2; r++) {
                    const int poff = (h0 + dy + r) * 58 + dx;
                    const __half* src = xqb + ((size_t)w16 * 3364 + poff) * 16;
                    BULK_G2S(sb + B_OFF(slot) + fw * 3584 + r * 1792, src, 1792, mb);
                }
            }
        };

        if (tid == 0) {
            fillStage(buf, 0);
            fillStage((buf + 1 >= NSTAGE) ? buf + 1 - NSTAGE : buf + 1, 1);
        }

        for (int ch = 0; ch < NCHUNK; ++ch) {
            MBAR_WAIT(sb + 8 * buf, phase[buf]);
            phase[buf] ^= 1;
            __syncthreads();

            if (tid == 0 && ch + 2 < NCHUNK)
                fillStage((buf + 2 >= NSTAGE) ? buf + 2 - NSTAGE : buf + 2, ch + 2);

            const char* Bb = smem + B_OFF(buf);
            const uint32_t aBase = sb + A_OFF(buf, ex);

#pragma unroll
            for (int kh2 = 0; kh2 < 2; kh2++) {
                uint32_t a_h[2][4];
#pragma unroll
                for (int mt = 0; mt < 2; mt++) {
                    int o = mo + mt * 16 + orow;
                    int s = kh2 * 2 + chalf;
                    uint32_t ah = aBase + o * 64 + ((s ^ ((o >> 1) & 3)) << 4);
                    ldm_x4(a_h[mt], ah);
                }
#pragma unroll
                for (int j = 0; j < 7; j++) {
                    const int col = po + j * 8 + g;
                    uint2 b01 = *(const uint2*)(Bb + kh2 * 3584 + col * 32 + tq * 8);
#pragma unroll
                    for (int mt = 0; mt < 2; mt++)
                        mma16816(acc[mt][j], a_h[mt], b01.x, b01.y);
                }
            }

            buf = (buf + 1 >= NSTAGE) ? 0 : buf + 1;
        }

        float* ob = out + (size_t)(2 * b + ex) * 128 * HW_;
#pragma unroll
        for (int mt = 0; mt < 2; mt++) {
#pragma unroll
            for (int j = 0; j < 7; j++) {
                int pc = n0 + po + j * 8 + tq * 2;
                int row0 = mo + mt * 16 + g;
                float2 v0 = make_float2(acc[mt][j][0], acc[mt][j][1]);
                float2 v1 = make_float2(acc[mt][j][2], acc[mt][j][3]);
                *(float2*)(ob + (size_t)row0 * HW_ + pc) = v0;
                *(float2*)(ob + (size_t)(row0 + 8) * HW_ + pc) = v1;
            }
        }
    }
}

// ----------------------------------------------------------------------------
extern "C" void kernel_launch(void* const* d_in, const int* in_sizes, int n_in,
                              void* d_out, int out_size) {
    const float* x     = (const float*)d_in[0];   // [32,128,56,56] f32
    const int*   gate  = (const int*)  d_in[1];   // [32,2] i32
    const float* wspec = (const float*)d_in[2];   // [8,128,128,3,3] f32
    const float* wch   = (const float*)d_in[3];   // [8,128,256,1,1] f32
    float* out = (float*)d_out;                   // [32,2,128,56,56] f32

    cudaFuncSetAttribute(conv_mma_kernel,
                         cudaFuncAttributeMaxDynamicSharedMemorySize, SMEM_TOTAL);

    reset_ctr_kernel<<<1, 1>>>();
    pack_kernel<<<dim3(8, 32), 256>>>(x);
    build_weff_kernel<<<dim3(9, 8), 256>>>(wspec, wch);
    conv_mma_kernel<<<148, 512, SMEM_TOTAL>>>(gate, out);
}

// round 11
// speedup vs baseline: 1.2300x; 1.2300x over previous
#include <cuda_runtime.h>
#include <cuda_fp16.h>
#include <cstdint>

#define HW_    3136
#define KTOT_  1152
#define NCHUNK 18          // 9 taps * 2 c-chunks of 64
#define NPIX_  112         // pixels per block tile = 2 image rows

// W smem-image: [e][tap][chunk2][o 128][8 segs x 8 halves], seg pre-swizzled (^ (o&7))
__device__ __align__(16) __half g_Wq[8 * 9 * 2 * 128 * 64];
// packed x: [b][window (8 of 16ch)][58*58 px][16 halves, permuted {0,1,8,9,2,3,10,11,4,5,12,13,6,7,14,15}]
__device__ __align__(16) __half g_xq[(size_t)32 * 8 * 3364 * 16];

__device__ __forceinline__ uint32_t smem_u32(const void* p) {
    uint32_t a;
    asm("{ .reg .u64 t; cvta.to.shared.u64 t, %1; cvt.u32.u64 %0, t; }" : "=r"(a) : "l"(p));
    return a;
}
#define MBAR_INIT(mb, c)  asm volatile("mbarrier.init.shared.b64 [%0], %1;" :: "r"(mb), "r"(c) : "memory")
#define MBAR_EXPECT(mb, tx) \
    asm volatile("mbarrier.arrive.expect_tx.shared.b64 _, [%0], %1;" :: "r"(mb), "r"(tx) : "memory")
#define BULK_G2S(dst, src, sz, mb) \
    asm volatile("cp.async.bulk.shared::cta.global.mbarrier::complete_tx::bytes [%0], [%1], %2, [%3];" \
                 :: "r"(dst), "l"(src), "r"(sz), "r"(mb) : "memory")

#define MBAR_WAIT(mb, ph) do {                                                            \
    uint32_t _m = (mb), _p = (ph), _d;                                                    \
    asm volatile("{ .reg .pred p; mbarrier.try_wait.parity.acquire.cta.shared::cta.b64 "  \
                 "p, [%1], %2; selp.b32 %0, 1, 0, p; }"                                   \
                 : "=r"(_d) : "r"(_m), "r"(_p) : "memory");                               \
    if (!_d) {                                                                            \
        asm volatile("{ .reg .pred P1;\n\t"                                               \
            "W_%=: mbarrier.try_wait.parity.acquire.cta.shared::cta.b64 P1, [%0], %1, 0x989680;\n\t" \
            "@P1 bra.uni D_%=;\n\t bra.uni W_%=;\n\t D_%=: }"                             \
            :: "r"(_m), "r"(_p) : "memory");                                              \
    } } while (0)

__device__ __forceinline__ void ldm_x4(uint32_t* r, uint32_t addr) {
    asm volatile("ldmatrix.sync.aligned.m8n8.x4.shared.b16 {%0,%1,%2,%3}, [%4];"
                 : "=r"(r[0]), "=r"(r[1]), "=r"(r[2]), "=r"(r[3]) : "r"(addr));
}
__device__ __forceinline__ void mma16816(float* d, const uint32_t* a, uint32_t b0, uint32_t b1) {
    asm volatile("mma.sync.aligned.m16n8k16.row.col.f32.f16.f16.f32 "
                 "{%0,%1,%2,%3}, {%4,%5,%6,%7}, {%8,%9}, {%0,%1,%2,%3};"
                 : "+f"(d[0]), "+f"(d[1]), "+f"(d[2]), "+f"(d[3])
                 : "r"(a[0]), "r"(a[1]), "r"(a[2]), "r"(a[3]), "r"(b0), "r"(b1));
}

// ---------------- Prep: pad + fp16 + permuted 16-channel pack ----------------
__global__ __launch_bounds__(256) void pack_kernel(const float* __restrict__ x) {
    const int wg = blockIdx.x;   // window 0..7
    const int b  = blockIdx.y;   // 0..31
    const float* xb = x + ((size_t)b * 128 + wg * 16) * HW_;
    uint32_t* dst = (uint32_t*)(g_xq + ((size_t)(b * 8 + wg)) * 3364 * 16);
    const int P[16] = {0, 1, 8, 9, 2, 3, 10, 11, 4, 5, 12, 13, 6, 7, 14, 15};
    for (int i = threadIdx.x; i < 3364; i += 256) {
        int r = i / 58;
        int c = i - r * 58;
        bool in = ((unsigned)(r - 1) < 56u) && ((unsigned)(c - 1) < 56u);
        int q = (r - 1) * 56 + (c - 1);
        uint32_t v[8];
#pragma unroll
        for (int s = 0; s < 8; s++) {
            float f0 = in ? xb[(size_t)P[2 * s] * HW_ + q] : 0.f;
            float f1 = in ? xb[(size_t)P[2 * s + 1] * HW_ + q] : 0.f;
            __half2 hp = __floats2half2_rn(f0, f1);
            v[s] = *(uint32_t*)&hp;
        }
        *(uint4*)(dst + (size_t)i * 8)     = make_uint4(v[0], v[1], v[2], v[3]);
        *(uint4*)(dst + (size_t)i * 8 + 4) = make_uint4(v[4], v[5], v[6], v[7]);
    }
}

// ---------------- Kernel A: build W_eff -> fp16, smem-image layout ----------------
__global__ __launch_bounds__(256) void build_weff_kernel(
    const float* __restrict__ wspec,   // [8][128][1152] (cdd = c*9 + tap)
    const float* __restrict__ wch)     // [8][128][256]
{
    const int e  = blockIdx.y;
    const int n0 = blockIdx.x * 128;

    __shared__ float As[8][128];
    __shared__ float Bs[8][128];

    const int t  = threadIdx.x;
    const int tm = t >> 4;
    const int tn = t & 15;

    float acc[8][8];
#pragma unroll
    for (int i = 0; i < 8; i++)
#pragma unroll
        for (int j = 0; j < 8; j++) acc[i][j] = 0.f;

    for (int kt = 0; kt < 16; ++kt) {
#pragma unroll
        for (int i = 0; i < 4; i++) {
            int idx = t + i * 256;
            int kl  = idx >> 7;
            int nl  = idx & 127;
            As[kl][nl] = wspec[(e * 128 + kt * 8 + kl) * 1152 + n0 + nl];
            Bs[kl][nl] = wch[(e * 128 + nl) * 256 + 128 + kt * 8 + kl];
        }
        __syncthreads();
#pragma unroll
        for (int kk = 0; kk < 8; kk++) {
            float a[8], bv[8];
            *(float4*)&a[0]  = *(const float4*)&As[kk][tm * 4];
            *(float4*)&a[4]  = *(const float4*)&As[kk][64 + tm * 4];
            *(float4*)&bv[0] = *(const float4*)&Bs[kk][tn * 4];
            *(float4*)&bv[4] = *(const float4*)&Bs[kk][64 + tn * 4];
#pragma unroll
            for (int i = 0; i < 8; i++)
#pragma unroll
                for (int j = 0; j < 8; j++) acc[i][j] += a[i] * bv[j];
        }
        __syncthreads();
    }

#pragma unroll
    for (int mi = 0; mi < 8; mi++) {
        int mrow = (mi < 4) ? (tm * 4 + mi) : (64 + tm * 4 + mi - 4);
        int cdd  = n0 + mrow;
        int cc   = cdd / 9;               // channel 0..127
        int tap  = cdd - cc * 9;
        bool center = (tap == 4);
        int chunk = cc >> 6;              // 0/1 (64-ch chunks)
        int pos   = cc & 63;
        int seg   = pos >> 3;             // 0..7
        int w8    = pos & 7;
#pragma unroll
        for (int j = 0; j < 8; j++) {
            int o = (j < 4) ? (tn * 4 + j) : (64 + tn * 4 + j - 4);
            float v = acc[mi][j];
            if (center) v += wch[(e * 128 + o) * 256 + cc];
            int segS = seg ^ (o & 7);     // ldmatrix bank swizzle (8 segs, 128B rows)
            size_t idx = ((((size_t)(e * 9 + tap) * 2 + chunk) * 128 + o) * 8 + segS) * 8 + w8;
            g_Wq[idx] = __float2half_rn(v);
        }
    }
}

// ---------------- Kernel B: fp16 mma.sync, K-chunks of 64, bulk-copy fills ----------------
// smem per slot:
//   A[expert 0..1]: 128 o x 128 B (pre-swizzled) -> 16384 each, 32768
//   B: [k-window (4)][px 112][16 halves]         -> 14336
#define A_SZ      16384
#define B_SZ      14336
#define SLOT_SZ   (2 * A_SZ + B_SZ)               // 47104
#define NSTAGE    3
#define SMEM_TOTAL (1024 + NSTAGE * SLOT_SZ)      // 142336
#define A_OFF(buf, ex) (1024 + (buf) * SLOT_SZ + (ex) * A_SZ)
#define B_OFF(buf)     (1024 + (buf) * SLOT_SZ + 32768)

__global__ __launch_bounds__(512, 1) void conv_mma_kernel(
    const int* __restrict__ gate,     // [32][2]
    float*     __restrict__ out)      // [32][2][128][56][56]
{
    extern __shared__ char smem[];
    const uint32_t sb = smem_u32(smem);

    const int tid  = threadIdx.x;
    const int wid  = tid >> 5;
    const int lane = tid & 31;
    const int g    = lane >> 2;
    const int tq   = lane & 3;
    const int b    = blockIdx.y;
    const int n0   = blockIdx.x * NPIX_;
    const int h0   = blockIdx.x * 2;

    const int ex   = wid >> 3;            // this warp's gate column
    const int e0   = gate[2 * b];
    const int e1   = gate[2 * b + 1];

    const __half* xqb = g_xq + (size_t)b * 8 * 3364 * 16;

    // warp tile within its expert half: 32(o) x 56(p)
    const int wg = wid & 7;
    const int mo = (wg >> 1) * 32;
    const int po = (wg & 1) * 56;
    const int orow  = lane & 15;
    const int chalf = lane >> 4;

    float acc[2][7][4];
#pragma unroll
    for (int mt = 0; mt < 2; mt++)
#pragma unroll
        for (int j = 0; j < 7; j++)
#pragma unroll
            for (int q = 0; q < 4; q++) acc[mt][j][q] = 0.f;

    if (tid == 0) {
        MBAR_INIT(sb + 0, 1);
        MBAR_INIT(sb + 8, 1);
        MBAR_INIT(sb + 16, 1);
    }
    __syncthreads();

    // producer: tid 0 issues 10 bulk copies per stage (2 A + 8 B)
    auto fillStage = [&](int slot, int ch) {
        const int tap = ch >> 1;
        const int cc  = ch & 1;
        const uint32_t mb = sb + 8 * slot;
        MBAR_EXPECT(mb, (uint32_t)SLOT_SZ);
        const __half* a0 = g_Wq + (((size_t)(e0 * 9 + tap) * 2 + cc) * 128) * 64;
        const __half* a1 = g_Wq + (((size_t)(e1 * 9 + tap) * 2 + cc) * 128) * 64;
        BULK_G2S(sb + A_OFF(slot, 0), a0, A_SZ, mb);
        BULK_G2S(sb + A_OFF(slot, 1), a1, A_SZ, mb);
        const int dy = tap / 3;
        const int dx = tap - 3 * dy;
#pragma unroll
        for (int fw = 0; fw < 4; fw++) {
            const int w16 = cc * 4 + fw;
#pragma unroll
            for (int r = 0; r < 2; r++) {
                const int poff = (h0 + dy + r) * 58 + dx;
                const __half* src = xqb + ((size_t)w16 * 3364 + poff) * 16;
                BULK_G2S(sb + B_OFF(slot) + fw * 3584 + r * 1792, src, 1792, mb);
            }
        }
    };

    if (tid == 0) {
        fillStage(0, 0);
        fillStage(1, 1);
    }

    int phase[NSTAGE] = {0, 0, 0};
    int buf = 0;
    for (int ch = 0; ch < NCHUNK; ++ch) {
        MBAR_WAIT(sb + 8 * buf, phase[buf]);
        phase[buf] ^= 1;
        __syncthreads();   // all threads done with slot (buf+2)%3 from iteration ch-1

        if (tid == 0 && ch + 2 < NCHUNK)
            fillStage((buf + 2 >= NSTAGE) ? buf + 2 - NSTAGE : buf + 2, ch + 2);

        const char* Bb = smem + B_OFF(buf);
        const uint32_t aBase = sb + A_OFF(buf, ex);

#pragma unroll
        for (int kh2 = 0; kh2 < 4; kh2++) {
            uint32_t a_h[2][4];
#pragma unroll
            for (int mt = 0; mt < 2; mt++) {
                int o = mo + mt * 16 + orow;
                int s = kh2 * 2 + chalf;
                uint32_t ah = aBase + o * 128 + ((s ^ (o & 7)) << 4);
                ldm_x4(a_h[mt], ah);
            }
#pragma unroll
            for (int j = 0; j < 7; j++) {
                const int col = po + j * 8 + g;
                uint2 b01 = *(const uint2*)(Bb + kh2 * 3584 + col * 32 + tq * 8);
#pragma unroll
                for (int mt = 0; mt < 2; mt++)
                    mma16816(acc[mt][j], a_h[mt], b01.x, b01.y);
            }
        }

        buf = (buf + 1 >= NSTAGE) ? 0 : buf + 1;
    }

    // ---- epilogue ----
    float* ob = out + (size_t)(2 * b + ex) * 128 * HW_;
#pragma unroll
    for (int mt = 0; mt < 2; mt++) {
#pragma unroll
        for (int j = 0; j < 7; j++) {
            int pc = n0 + po + j * 8 + tq * 2;
            int row0 = mo + mt * 16 + g;
            float2 v0 = make_float2(acc[mt][j][0], acc[mt][j][1]);
            float2 v1 = make_float2(acc[mt][j][2], acc[mt][j][3]);
            *(float2*)(ob + (size_t)row0 * HW_ + pc) = v0;
            *(float2*)(ob + (size_t)(row0 + 8) * HW_ + pc) = v1;
        }
    }
}

// ----------------------------------------------------------------------------
extern "C" void kernel_launch(void* const* d_in, const int* in_sizes, int n_in,
                              void* d_out, int out_size) {
    const float* x     = (const float*)d_in[0];   // [32,128,56,56] f32
    const int*   gate  = (const int*)  d_in[1];   // [32,2] i32
    const float* wspec = (const float*)d_in[2];   // [8,128,128,3,3] f32
    const float* wch   = (const float*)d_in[3];   // [8,128,256,1,1] f32
    float* out = (float*)d_out;                   // [32,2,128,56,56] f32

    cudaFuncSetAttribute(conv_mma_kernel,
                         cudaFuncAttributeMaxDynamicSharedMemorySize, SMEM_TOTAL);

    pack_kernel<<<dim3(8, 32), 256>>>(x);
    build_weff_kernel<<<dim3(9, 8), 256>>>(wspec, wch);
    conv_mma_kernel<<<dim3(28, 32), 512, SMEM_TOTAL>>>(gate, out);
}

// round 12
// speedup vs baseline: 1.3537x; 1.1006x over previous
#include <cuda_runtime.h>
#include <cuda_fp16.h>
#include <cstdint>

#define HW_    3136
#define KTOT_  1152
#define NCHUNK 9           // 9 taps, K=128 per stage
#define NPIX_  112         // pixels per block tile = 2 image rows

// W smem-image: [e][tap][o 128][16 segs x 8 halves], seg pre-swizzled (^ (o&7))
__device__ __align__(16) __half g_Wq[8 * 9 * 128 * 128];
// packed x: [b][window (8 of 16ch)][58*58 px][16 halves, permuted {0,1,8,9,2,3,10,11,4,5,12,13,6,7,14,15}]
__device__ __align__(16) __half g_xq[(size_t)32 * 8 * 3364 * 16];

__device__ __forceinline__ uint32_t smem_u32(const void* p) {
    uint32_t a;
    asm("{ .reg .u64 t; cvta.to.shared.u64 t, %1; cvt.u32.u64 %0, t; }" : "=r"(a) : "l"(p));
    return a;
}
#define MBAR_INIT(mb, c)  asm volatile("mbarrier.init.shared.b64 [%0], %1;" :: "r"(mb), "r"(c) : "memory")
#define MBAR_EXPECT(mb, tx) \
    asm volatile("mbarrier.arrive.expect_tx.shared.b64 _, [%0], %1;" :: "r"(mb), "r"(tx) : "memory")
#define BULK_G2S(dst, src, sz, mb) \
    asm volatile("cp.async.bulk.shared::cta.global.mbarrier::complete_tx::bytes [%0], [%1], %2, [%3];" \
                 :: "r"(dst), "l"(src), "r"(sz), "r"(mb) : "memory")

#define MBAR_WAIT(mb, ph) do {                                                            \
    uint32_t _m = (mb), _p = (ph), _d;                                                    \
    asm volatile("{ .reg .pred p; mbarrier.try_wait.parity.acquire.cta.shared::cta.b64 "  \
                 "p, [%1], %2; selp.b32 %0, 1, 0, p; }"                                   \
                 : "=r"(_d) : "r"(_m), "r"(_p) : "memory");                               \
    if (!_d) {                                                                            \
        asm volatile("{ .reg .pred P1;\n\t"                                               \
            "W_%=: mbarrier.try_wait.parity.acquire.cta.shared::cta.b64 P1, [%0], %1, 0x989680;\n\t" \
            "@P1 bra.uni D_%=;\n\t bra.uni W_%=;\n\t D_%=: }"                             \
            :: "r"(_m), "r"(_p) : "memory");                                              \
    } } while (0)

__device__ __forceinline__ void ldm_x4(uint32_t* r, uint32_t addr) {
    asm volatile("ldmatrix.sync.aligned.m8n8.x4.shared.b16 {%0,%1,%2,%3}, [%4];"
                 : "=r"(r[0]), "=r"(r[1]), "=r"(r[2]), "=r"(r[3]) : "r"(addr));
}
__device__ __forceinline__ void mma16816(float* d, const uint32_t* a, uint32_t b0, uint32_t b1) {
    asm volatile("mma.sync.aligned.m16n8k16.row.col.f32.f16.f16.f32 "
                 "{%0,%1,%2,%3}, {%4,%5,%6,%7}, {%8,%9}, {%0,%1,%2,%3};"
                 : "+f"(d[0]), "+f"(d[1]), "+f"(d[2]), "+f"(d[3])
                 : "r"(a[0]), "r"(a[1]), "r"(a[2]), "r"(a[3]), "r"(b0), "r"(b1));
}

// ---------------- Prep: pad + fp16 + permuted 16-channel pack ----------------
__global__ __launch_bounds__(256) void pack_kernel(const float* __restrict__ x) {
    const int wg = blockIdx.x;   // window 0..7
    const int b  = blockIdx.y;   // 0..31
    const float* xb = x + ((size_t)b * 128 + wg * 16) * HW_;
    uint32_t* dst = (uint32_t*)(g_xq + ((size_t)(b * 8 + wg)) * 3364 * 16);
    const int P[16] = {0, 1, 8, 9, 2, 3, 10, 11, 4, 5, 12, 13, 6, 7, 14, 15};
    for (int i = threadIdx.x; i < 3364; i += 256) {
        int r = i / 58;
        int c = i - r * 58;
        bool in = ((unsigned)(r - 1) < 56u) && ((unsigned)(c - 1) < 56u);
        int q = (r - 1) * 56 + (c - 1);
        uint32_t v[8];
#pragma unroll
        for (int s = 0; s < 8; s++) {
            float f0 = in ? xb[(size_t)P[2 * s] * HW_ + q] : 0.f;
            float f1 = in ? xb[(size_t)P[2 * s + 1] * HW_ + q] : 0.f;
            __half2 hp = __floats2half2_rn(f0, f1);
            v[s] = *(uint32_t*)&hp;
        }
        *(uint4*)(dst + (size_t)i * 8)     = make_uint4(v[0], v[1], v[2], v[3]);
        *(uint4*)(dst + (size_t)i * 8 + 4) = make_uint4(v[4], v[5], v[6], v[7]);
    }
}

// ---------------- Kernel A: build W_eff -> fp16, smem-image layout ----------------
__global__ __launch_bounds__(256) void build_weff_kernel(
    const float* __restrict__ wspec,   // [8][128][1152] (cdd = c*9 + tap)
    const float* __restrict__ wch)     // [8][128][256]
{
    const int e  = blockIdx.y;
    const int n0 = blockIdx.x * 128;

    __shared__ float As[8][128];
    __shared__ float Bs[8][128];

    const int t  = threadIdx.x;
    const int tm = t >> 4;
    const int tn = t & 15;

    float acc[8][8];
#pragma unroll
    for (int i = 0; i < 8; i++)
#pragma unroll
        for (int j = 0; j < 8; j++) acc[i][j] = 0.f;

    for (int kt = 0; kt < 16; ++kt) {
#pragma unroll
        for (int i = 0; i < 4; i++) {
            int idx = t + i * 256;
            int kl  = idx >> 7;
            int nl  = idx & 127;
            As[kl][nl] = wspec[(e * 128 + kt * 8 + kl) * 1152 + n0 + nl];
            Bs[kl][nl] = wch[(e * 128 + nl) * 256 + 128 + kt * 8 + kl];
        }
        __syncthreads();
#pragma unroll
        for (int kk = 0; kk < 8; kk++) {
            float a[8], bv[8];
            *(float4*)&a[0]  = *(const float4*)&As[kk][tm * 4];
            *(float4*)&a[4]  = *(const float4*)&As[kk][64 + tm * 4];
            *(float4*)&bv[0] = *(const float4*)&Bs[kk][tn * 4];
            *(float4*)&bv[4] = *(const float4*)&Bs[kk][64 + tn * 4];
#pragma unroll
            for (int i = 0; i < 8; i++)
#pragma unroll
                for (int j = 0; j < 8; j++) acc[i][j] += a[i] * bv[j];
        }
        __syncthreads();
    }

#pragma unroll
    for (int mi = 0; mi < 8; mi++) {
        int mrow = (mi < 4) ? (tm * 4 + mi) : (64 + tm * 4 + mi - 4);
        int cdd  = n0 + mrow;
        int cc   = cdd / 9;               // channel 0..127
        int tap  = cdd - cc * 9;
        bool center = (tap == 4);
        int seg   = cc >> 3;              // 0..15
        int w8    = cc & 7;
#pragma unroll
        for (int j = 0; j < 8; j++) {
            int o = (j < 4) ? (tn * 4 + j) : (64 + tn * 4 + j - 4);
            float v = acc[mi][j];
            if (center) v += wch[(e * 128 + o) * 256 + cc];
            int segS = seg ^ (o & 7);     // ldmatrix bank swizzle (16 segs, 256B rows)
            size_t idx = (((size_t)(e * 9 + tap) * 128 + o) * 16 + segS) * 8 + w8;
            g_Wq[idx] = __float2half_rn(v);
        }
    }
}

// ---------------- Kernel B: fp16 mma.sync, K=128 per stage, 2-slot ring ----------------
// smem per slot:
//   A[expert 0..1]: 128 o x 256 B (pre-swizzled)     -> 32768 each, 65536
//   B: [window (8)][114 px (2 rows + seam)][16 h]    -> 29184
#define A_SZ      32768
#define B_SZ      29184
#define SLOT_SZ   (2 * A_SZ + B_SZ)               // 94720
#define NSTAGE    2
#define SMEM_TOTAL (1024 + NSTAGE * SLOT_SZ)      // 190464
#define A_OFF(buf, ex) (1024 + (buf) * SLOT_SZ + (ex) * A_SZ)
#define B_OFF(buf)     (1024 + (buf) * SLOT_SZ + 65536)

__global__ __launch_bounds__(512, 1) void conv_mma_kernel(
    const int* __restrict__ gate,     // [32][2]
    float*     __restrict__ out)      // [32][2][128][56][56]
{
    extern __shared__ char smem[];
    const uint32_t sb = smem_u32(smem);

    const int tid  = threadIdx.x;
    const int wid  = tid >> 5;
    const int lane = tid & 31;
    const int g    = lane >> 2;
    const int tq   = lane & 3;
    const int b    = blockIdx.y;
    const int n0   = blockIdx.x * NPIX_;
    const int h0   = blockIdx.x * 2;

    const int ex   = wid >> 3;            // this warp's gate column
    const int e0   = gate[2 * b];
    const int e1   = gate[2 * b + 1];

    const __half* xqb = g_xq + (size_t)b * 8 * 3364 * 16;

    // warp tile within its expert half: 32(o) x 56(p)
    const int wg = wid & 7;
    const int mo = (wg >> 1) * 32;
    const int po = (wg & 1) * 56;
    const int colb = po ? 58 : 0;         // +2 seam offset for second image row
    const int orow  = lane & 15;
    const int chalf = lane >> 4;

    float acc[2][7][4];
#pragma unroll
    for (int mt = 0; mt < 2; mt++)
#pragma unroll
        for (int j = 0; j < 7; j++)
#pragma unroll
            for (int q = 0; q < 4; q++) acc[mt][j][q] = 0.f;

    if (tid == 0) {
        MBAR_INIT(sb + 0, 1);
        MBAR_INIT(sb + 8, 1);
    }
    __syncthreads();

    // producer: tid 0 issues 10 bulk copies per stage (2 A + 8 B)
    auto fillStage = [&](int slot, int tap) {
        const uint32_t mb = sb + 8 * slot;
        MBAR_EXPECT(mb, (uint32_t)SLOT_SZ);
        const __half* a0 = g_Wq + ((size_t)(e0 * 9 + tap) * 128) * 128;
        const __half* a1 = g_Wq + ((size_t)(e1 * 9 + tap) * 128) * 128;
        BULK_G2S(sb + A_OFF(slot, 0), a0, A_SZ, mb);
        BULK_G2S(sb + A_OFF(slot, 1), a1, A_SZ, mb);
        const int dy = tap / 3;
        const int dx = tap - 3 * dy;
        const int poff = (h0 + dy) * 58 + dx;    // first row; 114 px span covers both rows
#pragma unroll
        for (int fw = 0; fw < 8; fw++) {
            const __half* src = xqb + ((size_t)fw * 3364 + poff) * 16;
            BULK_G2S(sb + B_OFF(slot) + fw * 3648, src, 3648, mb);
        }
    };

    if (tid == 0) {
        fillStage(0, 0);
        fillStage(1, 1);
    }

    int phase[NSTAGE] = {0, 0};
    int buf = 0;
    for (int tap = 0; tap < NCHUNK; ++tap) {
        MBAR_WAIT(sb + 8 * buf, phase[buf]);
        phase[buf] ^= 1;

        const char* Bb = smem + B_OFF(buf);
        const uint32_t aBase = sb + A_OFF(buf, ex);

#pragma unroll
        for (int kh2 = 0; kh2 < 8; kh2++) {
            uint32_t a_h[2][4];
#pragma unroll
            for (int mt = 0; mt < 2; mt++) {
                int o = mo + mt * 16 + orow;
                int s = kh2 * 2 + chalf;
                uint32_t ah = aBase + o * 256 + ((s ^ (o & 7)) << 4);
                ldm_x4(a_h[mt], ah);
            }
#pragma unroll
            for (int j = 0; j < 7; j++) {
                const int col = colb + j * 8 + g;
                uint2 b01 = *(const uint2*)(Bb + kh2 * 3648 + col * 32 + tq * 8);
#pragma unroll
                for (int mt = 0; mt < 2; mt++)
                    mma16816(acc[mt][j], a_h[mt], b01.x, b01.y);
            }
        }

        __syncthreads();                 // all threads done reading this slot
        if (tid == 0 && tap + 2 < NCHUNK)
            fillStage(buf, tap + 2);     // refill the slot just consumed

        buf ^= 1;
    }

    // ---- epilogue ----
    float* ob = out + (size_t)(2 * b + ex) * 128 * HW_;
#pragma unroll
    for (int mt = 0; mt < 2; mt++) {
#pragma unroll
        for (int j = 0; j < 7; j++) {
            int pc = n0 + po + j * 8 + tq * 2;
            int row0 = mo + mt * 16 + g;
            float2 v0 = make_float2(acc[mt][j][0], acc[mt][j][1]);
            float2 v1 = make_float2(acc[mt][j][2], acc[mt][j][3]);
            *(float2*)(ob + (size_t)row0 * HW_ + pc) = v0;
            *(float2*)(ob + (size_t)(row0 + 8) * HW_ + pc) = v1;
        }
    }
}

// ----------------------------------------------------------------------------
extern "C" void kernel_launch(void* const* d_in, const int* in_sizes, int n_in,
                              void* d_out, int out_size) {
    const float* x     = (const float*)d_in[0];   // [32,128,56,56] f32
    const int*   gate  = (const int*)  d_in[1];   // [32,2] i32
    const float* wspec = (const float*)d_in[2];   // [8,128,128,3,3] f32
    const float* wch   = (const float*)d_in[3];   // [8,128,256,1,1] f32
    float* out = (float*)d_out;                   // [32,2,128,56,56] f32

    cudaFuncSetAttribute(conv_mma_kernel,
                         cudaFuncAttributeMaxDynamicSharedMemorySize, SMEM_TOTAL);

    pack_kernel<<<dim3(8, 32), 256>>>(x);
    build_weff_kernel<<<dim3(9, 8), 256>>>(wspec, wch);
    conv_mma_kernel<<<dim3(28, 32), 512, SMEM_TOTAL>>>(gate, out);
}